// round 1
// baseline (speedup 1.0000x reference)
#include <cuda_runtime.h>
#include <cuda_bf16.h>
#include <cstdint>

// ---------------------------------------------------------------------------
// CopyNet pointer-generator mix.
//   out[b,t,v] = p_gen[b,t] * (v < V ? dist[b,t,v] : 0)
//              + (1 - p_gen[b,t]) * sum_{s: pointer[b,s]==v} alph[b,s,t]
//
// Kernel 1: streaming scale + zero-pad (float4 vectorized). HBM-bound.
// Kernel 2: scatter-add of 1M attention weights via atomicAdd (spread addrs).
// ---------------------------------------------------------------------------

// Kernel 1: rows = B*L_DEC, each row has Vext4 float4 slots; first V4 come
// from dist scaled by p_gen, rest are zero.
__global__ void copynet_scale_kernel(const float* __restrict__ dist,
                                     const float* __restrict__ p_gen,
                                     float* __restrict__ out,
                                     int V4, int Vext4)
{
    int row  = blockIdx.y;                    // b*L_DEC + t
    int col4 = blockIdx.x * blockDim.x + threadIdx.x;
    if (col4 >= Vext4) return;

    float pg = __ldg(&p_gen[row]);

    float4 r;
    if (col4 < V4) {
        const float4* src = reinterpret_cast<const float4*>(dist);
        float4 d = __ldg(&src[(size_t)row * V4 + col4]);
        r.x = pg * d.x; r.y = pg * d.y; r.z = pg * d.z; r.w = pg * d.w;
    } else {
        r.x = r.y = r.z = r.w = 0.0f;
    }
    reinterpret_cast<float4*>(out)[(size_t)row * Vext4 + col4] = r;
}

// Scalar fallback (non-multiple-of-4 vocab sizes).
__global__ void copynet_scale_scalar_kernel(const float* __restrict__ dist,
                                            const float* __restrict__ p_gen,
                                            float* __restrict__ out,
                                            int V, int Vext)
{
    int row = blockIdx.y;
    int col = blockIdx.x * blockDim.x + threadIdx.x;
    if (col >= Vext) return;
    float pg = __ldg(&p_gen[row]);
    float v  = (col < V) ? pg * __ldg(&dist[(size_t)row * V + col]) : 0.0f;
    out[(size_t)row * Vext + col] = v;
}

// Kernel 2: one thread per (b, s, t). alph layout [B, L_SRC, L_DEC] so the
// linear thread index IS the alph index (coalesced). All 32 lanes of a warp
// share (b,s) -> same pointer value, but t differs -> 32 distinct output
// addresses with stride Vext*4 bytes (no same-address contention).
__global__ void copynet_scatter_kernel(const float* __restrict__ alph,
                                       const float* __restrict__ p_gen,
                                       const int*   __restrict__ pointer,
                                       float* __restrict__ out,
                                       int L_DEC, int L_SRC, int Vext,
                                       int total)
{
    int idx = blockIdx.x * blockDim.x + threadIdx.x;
    if (idx >= total) return;

    int t  = idx % L_DEC;
    int bs = idx / L_DEC;          // b*L_SRC + s
    int b  = bs / L_SRC;

    float a   = __ldg(&alph[idx]);
    int   ptr = __ldg(&pointer[bs]);
    int   bt  = b * L_DEC + t;
    float pg  = __ldg(&p_gen[bt]);

    atomicAdd(&out[(size_t)bt * Vext + ptr], (1.0f - pg) * a);
}

extern "C" void kernel_launch(void* const* d_in, const int* in_sizes, int n_in,
                              void* d_out, int out_size)
{
    // metadata order: dist_t, p_gen, alph_t, batch_vocab, pointer
    const float* dist    = (const float*)d_in[0];
    const float* p_gen   = (const float*)d_in[1];
    const float* alph    = (const float*)d_in[2];
    const int*   pointer = (const int*)d_in[4];
    float*       out     = (float*)d_out;

    // Derive shapes from sizes.
    int BT    = in_sizes[1];                 // B * L_DEC   (2048)
    int Vext  = in_sizes[3];                 // 32128
    int BS    = in_sizes[4];                 // B * L_SRC   (4096)
    int L_DEC = in_sizes[2] / BS;            // 256
    int B     = BT / L_DEC;                  // 8
    int L_SRC = BS / B;                      // 512
    int V     = in_sizes[0] / BT;            // 32000

    const int TPB = 256;

    if ((V % 4 == 0) && (Vext % 4 == 0)) {
        int V4 = V / 4, Vext4 = Vext / 4;
        dim3 grid((Vext4 + TPB - 1) / TPB, BT);
        copynet_scale_kernel<<<grid, TPB>>>(dist, p_gen, out, V4, Vext4);
    } else {
        dim3 grid((Vext + TPB - 1) / TPB, BT);
        copynet_scale_scalar_kernel<<<grid, TPB>>>(dist, p_gen, out, V, Vext);
    }

    int total = B * L_SRC * L_DEC;           // 1,048,576
    int blocks = (total + TPB - 1) / TPB;
    copynet_scatter_kernel<<<blocks, TPB>>>(alph, p_gen, pointer, out,
                                            L_DEC, L_SRC, Vext, total);
}